// round 15
// baseline (speedup 1.0000x reference)
#include <cuda_runtime.h>
#include <math.h>

#define NN 10000
#define NSLICE 28
#define NCHUNK 5
#define NB 140
#define NT 1024
#define OUTB 2048              // outputs per chunk (2 per thread)
#define MAXR 121               // max table rows any block needs
#define TW2 200                // u16 row width (even)
#define TABW (199 * 100)       // u32 words per table copy = 19900
#define AWORDS (MAXR * 100)    // u32 words per smem copy = 12100
#define DB (AWORDS * 4)        // byte offset of smem copy B = 48400
#define SLIST_OFF (2 * DB)     // 96800, 16B aligned
#define SLIST_MAX 512
#define SMEM_BYTES (SLIST_OFF + SLIST_MAX * 4)
#define QSCALE 448.0
#define SSCALE 512.0

// ---------------------------------------------------------------------------
// Compile-time tables: quantized distance table (copies A and B) + integer
// A-row table (x512). Generated by constexpr Newton sqrt (double precision).
// ---------------------------------------------------------------------------
constexpr double csqrt(double x) {
    if (x <= 0.0) return 0.0;
    double r = 1.0;
    while (r * r < x) r *= 2.0;
    for (int i = 0; i < 8; ++i) r = 0.5 * (r + x / r);
    return r;
}

struct alignas(16) Tables {
    unsigned tA[TABW];
    unsigned tB[TABW];
    unsigned Ai[NN];           // round(A * 512)
};

constexpr Tables make_tables() {
    Tables T{};
    unsigned short v[2 * TABW] = {};
    for (int t = 0; t < 2 * TABW; ++t) {
        int a = t / TW2, c = t - a * TW2;
        double dx = (double)(a - 99), dy = (double)(c - 99);
        double s = csqrt(dx * dx + dy * dy);
        v[t] = (unsigned short)(s * QSCALE + 0.5);
    }
    for (int w = 0; w < TABW; ++w) {
        T.tA[w] = (unsigned)v[2 * w] | ((unsigned)v[2 * w + 1] << 16);
        int t1 = (2 * w + 2 < 2 * TABW) ? (2 * w + 2) : (2 * w + 1);
        T.tB[w] = (unsigned)v[2 * w + 1] | ((unsigned)v[t1] << 16);
    }
    for (int di = 0; di < 100; ++di) {
        double pref[100] = {};
        double run = 0.0;
        for (int d = 1; d < 100; ++d) {
            run += csqrt((double)(di * di + d * d));
            pref[d] = run;
        }
        for (int j = 0; j < 100; ++j) {
            double a = (double)di + pref[j] + pref[99 - j];
            T.Ai[di * 100 + j] = (unsigned)(a * SSCALE + 0.5);
        }
    }
    return T;
}

__device__ const Tables c_tab = make_tables();

__device__ unsigned g_Ti[10240];   // integer T accumulators (zero-init, self-cleaning)
__device__ unsigned g_Si[10240];   // integer S accumulators
__device__ float g_cs[NCHUNK];
__device__ int   g_dc[NCHUNK];     // per-chunk arrival counters
__device__ int   g_done2;

// ---------------------------------------------------------------------------
// Single kernel. Integer atomics make slice accumulation order-independent
// (deterministic). Chunk-last block reduces 16KB; overall-last writes out.
// ---------------------------------------------------------------------------
__global__ __launch_bounds__(NT, 1) void k_all(const float* __restrict__ prob,
                                               const float* __restrict__ gt,
                                               float* __restrict__ out) {
    extern __shared__ unsigned char smraw[];
    unsigned* wA = (unsigned*)smraw;
    unsigned* wB = (unsigned*)(smraw + DB);
    int* slist = (int*)(smraw + SLIST_OFF);

    __shared__ int swtot[32];
    __shared__ int swoff[32];
    __shared__ int sh_n;
    __shared__ int lastFlag;
    __shared__ float wsum[32];

    const int bid = blockIdx.x;
    const int tid = threadIdx.x;
    const int warp = tid >> 5, lane = tid & 31;

    const int chunk = bid / NSLICE;
    const int s = bid - chunk * NSLICE;
    const int o0 = chunk * OUTB;
    int i1hi = (o0 + OUTB - 1) / 100; if (i1hi > 99) i1hi = 99;
    const int i1lo = o0 / 100;
    const int rlo = 99 - i1hi;
    const int nrows = 100 + (i1hi - i1lo);
    const int nW = nrows * 100;
    const int badj = rlo * TW2 + 1;

    // ---- issue gt loads first (MLP=10); latency hides under staging ----
    float vv[10];
    const int o_base = warp * 320 + lane;   // warp owns [320w, 320w+320)
    #pragma unroll
    for (int it = 0; it < 10; ++it) {
        int o = o_base + it * 32;
        vv[it] = (o < NN) ? gt[o] : 0.0f;
    }
    // warm L2 with this chunk's prob lines (used by the tail reduce)
    if (tid < 64) {
        const char* p = (const char*)(prob + chunk * OUTB) + tid * 128;
        asm volatile("prefetch.global.L2 [%0];" :: "l"(p));
    }

    // ---- stage table window from L2 (static const data) into smem ----
    {
        const int4* srcA = (const int4*)(c_tab.tA + rlo * 100);
        const int4* srcB = (const int4*)(c_tab.tB + rlo * 100);
        int4* dA = (int4*)wA;
        int4* dB = (int4*)wB;
        int nv = nW >> 2;
        for (int k2 = tid; k2 < nv; k2 += NT) {
            dA[k2] = srcA[k2];
            dB[k2] = srcB[k2];
        }
    }

    // ---- per-block deterministic compaction of py = (gt >= 0.5) ----
    unsigned bal[10];
    #pragma unroll
    for (int it = 0; it < 10; ++it) {
        int o = o_base + it * 32;
        bool p = (o < NN) && (vv[it] >= 0.5f);
        bal[it] = __ballot_sync(0xffffffffu, p);
    }
    int pre[10]; int run = 0;
    #pragma unroll
    for (int it = 0; it < 10; ++it) { pre[it] = run; run += __popc(bal[it]); }
    if (lane == 0) swtot[warp] = run;
    __syncthreads();
    if (warp == 0) {
        int t = swtot[lane];
        int incl = t;
        #pragma unroll
        for (int d = 1; d < 32; d <<= 1) {
            int v = __shfl_up_sync(0xffffffffu, incl, d);
            if (lane >= d) incl += v;
        }
        swoff[lane] = incl - t;
        if (lane == 31) sh_n = incl;
    }
    __syncthreads();
    const int n = sh_n;
    const int e0 = (s * n) / NSLICE;
    const int e1 = ((s + 1) * n) / NSLICE;
    const int cnt = e1 - e0;
    {
        int base = swoff[warp];
        #pragma unroll
        for (int it = 0; it < 10; ++it) {
            unsigned b = bal[it];
            if ((b >> lane) & 1u) {
                int pos = base + pre[it] + __popc(b & ((1u << lane) - 1u));
                if (pos >= e0 && pos < e1) {
                    int o = o_base + it * 32;
                    int i2 = o / 100, j2 = o - i2 * 100;
                    int F = (i2 + 99) * TW2 + (j2 + 99) - badj;
                    int p2 = F & 1;
                    slist[pos - e0] = 2 * (F - p2) + p2 * DB;
                }
            }
        }
    }
    __syncthreads();

    // ---- main sparse DP2A accumulate (2 outputs per thread) ----
    int oe = o0 + 2 * tid;
    bool valid = (oe < NN);
    int oc = valid ? oe : (NN - 2);
    int i1 = oc / 100;
    int j1 = oc - i1 * 100;
    int qq = j1 >> 1;

    unsigned baseA;
    asm("{ .reg .u64 t; cvta.to.shared.u64 t, %1; cvt.u32.u64 %0, t; }"
        : "=r"(baseA) : "l"(smraw));
    unsigned tb = baseA - 400u * (unsigned)i1 - 4u * (unsigned)qq;

    unsigned aE0 = 0, aE1 = 0, aO0 = 0, aO1 = 0;
    int k = 0;
    int n8 = cnt & ~7;
    for (; k < n8; k += 8) {
        int4 ea = *(const int4*)(slist + k);
        int4 eb = *(const int4*)(slist + k + 4);
        unsigned w0, w1, w2, w3, w4, w5, w6, w7;
        asm("ld.shared.u32 %0,[%1];" : "=r"(w0) : "r"(tb + (unsigned)ea.x));
        asm("ld.shared.u32 %0,[%1];" : "=r"(w1) : "r"(tb + (unsigned)ea.y));
        asm("ld.shared.u32 %0,[%1];" : "=r"(w2) : "r"(tb + (unsigned)ea.z));
        asm("ld.shared.u32 %0,[%1];" : "=r"(w3) : "r"(tb + (unsigned)ea.w));
        asm("ld.shared.u32 %0,[%1];" : "=r"(w4) : "r"(tb + (unsigned)eb.x));
        asm("ld.shared.u32 %0,[%1];" : "=r"(w5) : "r"(tb + (unsigned)eb.y));
        asm("ld.shared.u32 %0,[%1];" : "=r"(w6) : "r"(tb + (unsigned)eb.z));
        asm("ld.shared.u32 %0,[%1];" : "=r"(w7) : "r"(tb + (unsigned)eb.w));
        aE0 = __dp2a_lo(w0, 0x0100u, aE0); aO0 = __dp2a_lo(w0, 0x0001u, aO0);
        aE1 = __dp2a_lo(w1, 0x0100u, aE1); aO1 = __dp2a_lo(w1, 0x0001u, aO1);
        aE0 = __dp2a_lo(w2, 0x0100u, aE0); aO0 = __dp2a_lo(w2, 0x0001u, aO0);
        aE1 = __dp2a_lo(w3, 0x0100u, aE1); aO1 = __dp2a_lo(w3, 0x0001u, aO1);
        aE0 = __dp2a_lo(w4, 0x0100u, aE0); aO0 = __dp2a_lo(w4, 0x0001u, aO0);
        aE1 = __dp2a_lo(w5, 0x0100u, aE1); aO1 = __dp2a_lo(w5, 0x0001u, aO1);
        aE0 = __dp2a_lo(w6, 0x0100u, aE0); aO0 = __dp2a_lo(w6, 0x0001u, aO0);
        aE1 = __dp2a_lo(w7, 0x0100u, aE1); aO1 = __dp2a_lo(w7, 0x0001u, aO1);
    }
    for (; k < cnt; ++k) {
        unsigned w0;
        asm("ld.shared.u32 %0,[%1];" : "=r"(w0) : "r"(tb + (unsigned)slist[k]));
        aE0 = __dp2a_lo(w0, 0x0100u, aE0);
        aO0 = __dp2a_lo(w0, 0x0001u, aO0);
    }
    unsigned Ti_e = aE0 + aE1;
    unsigned Ti_o = aO0 + aO1;

    // slice partial of the integer rowsum S for both outputs (exact ints)
    int i2a = (100 * s) / NSLICE;
    int i2b = (100 * (s + 1)) / NSLICE;
    unsigned Si_e = 0, Si_o = 0;
    const uint2* A2 = (const uint2*)c_tab.Ai;
    for (int i2 = i2a; i2 < i2b; ++i2) {
        int di = i1 - i2; if (di < 0) di = -di;
        uint2 av = A2[di * 50 + qq];
        Si_e += av.x; Si_o += av.y;
    }

    if (valid) {
        atomicAdd(&g_Ti[oe],     Ti_e);
        atomicAdd(&g_Ti[oe + 1], Ti_o);
        atomicAdd(&g_Si[oe],     Si_e);
        atomicAdd(&g_Si[oe + 1], Si_o);
    }

    // ---- chunk-last block reduces its chunk (16KB), then zeroes it ----
    __threadfence();
    __syncthreads();
    if (tid == 0) {
        int fin = atomicAdd(&g_dc[chunk], 1);
        lastFlag = (fin == NSLICE - 1);
    }
    __syncthreads();
    if (lastFlag) {
        __threadfence();                       // acquire all atomics
        int oT = chunk * OUTB + 2 * tid;       // this chunk's output pair
        float ls = 0.f;
        uint2 ti = *(const uint2*)&g_Ti[oT];
        uint2 si = *(const uint2*)&g_Si[oT];
        if (oT < NN) {
            float2 pr = *(const float2*)&prob[oT];
            float pxe = (pr.x >= 0.5f) ? 1.0f : 0.0f;
            float pxo = (pr.y >= 0.5f) ? 1.0f : 0.0f;
            float Te = __uint2float_rn(ti.x) * (float)(1.0 / QSCALE);
            float To = __uint2float_rn(ti.y) * (float)(1.0 / QSCALE);
            float Se = __uint2float_rn(si.x) * (float)(1.0 / SSCALE);
            float So = __uint2float_rn(si.y) * (float)(1.0 / SSCALE);
            ls = fabsf(pxe * Se - Te) + fabsf(pxo * So - To);
        }
        // self-clean for graph replay (no other block touches this region now)
        *(uint2*)&g_Ti[oT] = make_uint2(0u, 0u);
        *(uint2*)&g_Si[oT] = make_uint2(0u, 0u);

        #pragma unroll
        for (int off = 16; off; off >>= 1)
            ls += __shfl_down_sync(0xffffffffu, ls, off);
        if (lane == 0) wsum[warp] = ls;
        __syncthreads();
        if (tid == 0) {
            float t = 0.f;
            #pragma unroll
            for (int w = 0; w < 32; ++w) t += wsum[w];
            g_cs[chunk] = t;
            g_dc[chunk] = 0;                   // replay-safe reset
            __threadfence();
            int fin2 = atomicAdd(&g_done2, 1);
            if (fin2 == NCHUNK - 1) {
                __threadfence();
                float tt = 0.f;
                #pragma unroll
                for (int c = 0; c < NCHUNK; ++c) tt += g_cs[c];
                out[0] = tt * (float)(1.0 / ((double)NN * (double)NN));
                g_done2 = 0;
                __threadfence();
            }
        }
    }
}

extern "C" void kernel_launch(void* const* d_in, const int* in_sizes, int n_in,
                              void* d_out, int out_size) {
    const float* prob = (const float*)d_in[0];
    const float* gt   = (const float*)d_in[1];
    float* out = (float*)d_out;

    cudaFuncSetAttribute(k_all, cudaFuncAttributeMaxDynamicSharedMemorySize, SMEM_BYTES);
    k_all<<<NB, NT, SMEM_BYTES>>>(prob, gt, out);
}